// round 1
// baseline (speedup 1.0000x reference)
#include <cuda_runtime.h>

// LorenzPINN: per-row forward + JVP of a 1->20->20->20->20->3 tanh MLP,
// then Lorenz residuals. fp32, packed f32x2 FMA (value+tangent share weights).

#define W 20
typedef unsigned long long u64;

__device__ __forceinline__ u64 pack2(float lo, float hi) {
    u64 r; asm("mov.b64 %0,{%1,%2};" : "=l"(r) : "f"(lo), "f"(hi)); return r;
}
__device__ __forceinline__ void unpack2(u64 v, float& lo, float& hi) {
    asm("mov.b64 {%0,%1},%2;" : "=f"(lo), "=f"(hi) : "l"(v));
}
__device__ __forceinline__ u64 ffma2(u64 a, u64 b, u64 c) {
    u64 d; asm("fma.rn.f32x2 %0,%1,%2,%3;" : "=l"(d) : "l"(a), "l"(b), "l"(c)); return d;
}

// Exact-form tanh: 1 - 2/(e^{2x}+1). Saturates correctly for |x| large
// (exp->inf => 1, exp->0 => -1). Abs error ~1e-7 (MUFU EX2+RCP).
__device__ __forceinline__ float fast_tanh(float x) {
    float e = __expf(2.0f * x);
    return 1.0f - __fdividef(2.0f, e + 1.0f);
}

// One hidden layer: (h,dh) packed in hd[], weights pre-duplicated in shared.
__device__ __forceinline__ void layer(u64 (&hd)[W], const u64* __restrict__ sw,
                                      const float* __restrict__ sb) {
    u64 nhd[W];
#pragma unroll
    for (int j = 0; j < W; j++) {
        u64 acc = pack2(sb[j], 0.0f);
#pragma unroll
        for (int k = 0; k < W; k++)
            acc = ffma2(hd[k], sw[j * W + k], acc);
        float z, dz; unpack2(acc, z, dz);
        float th = fast_tanh(z);
        nhd[j] = pack2(th, (1.0f - th * th) * dz);
    }
#pragma unroll
    for (int j = 0; j < W; j++) hd[j] = nhd[j];
}

__global__ __launch_bounds__(256)
void lorenz_pinn_kernel(const float* __restrict__ t,
                        const float* __restrict__ W1, const float* __restrict__ b1,
                        const float* __restrict__ W2, const float* __restrict__ b2,
                        const float* __restrict__ W3, const float* __restrict__ b3,
                        const float* __restrict__ W4, const float* __restrict__ b4,
                        const float* __restrict__ Wo, const float* __restrict__ bo,
                        const float* __restrict__ c1p, const float* __restrict__ c2p,
                        const float* __restrict__ c3p,
                        float* __restrict__ out, int n) {
    __shared__ u64 sW2[W * W], sW3[W * W], sW4[W * W], sWo[3 * W];
    __shared__ float sW1[W], sb1[W], sb2[W], sb3[W], sb4[W], sbo[4];

    // Cooperative weight load: duplicated (w,w) pairs, transposed to [j][k].
    for (int idx = threadIdx.x; idx < W * W; idx += blockDim.x) {
        int j = idx / W, k = idx % W;
        float w2 = W2[k * W + j]; sW2[idx] = pack2(w2, w2);
        float w3 = W3[k * W + j]; sW3[idx] = pack2(w3, w3);
        float w4 = W4[k * W + j]; sW4[idx] = pack2(w4, w4);
    }
    if (threadIdx.x < 3 * W) {
        int c = threadIdx.x / W, k = threadIdx.x % W;
        float w = Wo[k * 3 + c];
        sWo[threadIdx.x] = pack2(w, w);
    }
    if (threadIdx.x < W) {
        sW1[threadIdx.x] = W1[threadIdx.x];
        sb1[threadIdx.x] = b1[threadIdx.x];
        sb2[threadIdx.x] = b2[threadIdx.x];
        sb3[threadIdx.x] = b3[threadIdx.x];
        sb4[threadIdx.x] = b4[threadIdx.x];
    }
    if (threadIdx.x < 3) sbo[threadIdx.x] = bo[threadIdx.x];
    __syncthreads();

    int i = blockIdx.x * blockDim.x + threadIdx.x;
    if (i >= n) return;

    float tv = t[i];
    float C1 = __ldg(c1p), C2 = __ldg(c2p), C3 = __ldg(c3p);

    // Layer 1: pre = t*W1 + b1, dpre = W1 (tangent of t is 1).
    u64 hd[W];
#pragma unroll
    for (int j = 0; j < W; j++) {
        float w = sW1[j];
        float th = fast_tanh(fmaf(tv, w, sb1[j]));
        hd[j] = pack2(th, (1.0f - th * th) * w);
    }

    layer(hd, sW2, sb2);
    layer(hd, sW3, sb3);
    layer(hd, sW4, sb4);

    // Output head (3 units, no activation).
    float o[3], d[3];
#pragma unroll
    for (int c = 0; c < 3; c++) {
        u64 acc = pack2(sbo[c], 0.0f);
#pragma unroll
        for (int k = 0; k < W; k++)
            acc = ffma2(hd[k], sWo[c * W + k], acc);
        unpack2(acc, o[c], d[c]);
    }

    float x = o[0], y = o[1], z = o[2];
    float dx = d[0], dy = d[1], dz = d[2];
    float fx = dx - C1 * (y - x);
    float fy = dy - x * (C2 - z) + y;
    float fz = dz - x * y + C3 * z;

    float* po = out + (size_t)i * 6;
    po[0] = x; po[1] = y; po[2] = z;
    po[3] = fx; po[4] = fy; po[5] = fz;
}

extern "C" void kernel_launch(void* const* d_in, const int* in_sizes, int n_in,
                              void* d_out, int out_size) {
    const float* t  = (const float*)d_in[0];
    const float* W1 = (const float*)d_in[1];
    const float* b1 = (const float*)d_in[2];
    const float* W2 = (const float*)d_in[3];
    const float* b2 = (const float*)d_in[4];
    const float* W3 = (const float*)d_in[5];
    const float* b3 = (const float*)d_in[6];
    const float* W4 = (const float*)d_in[7];
    const float* b4 = (const float*)d_in[8];
    const float* Wo = (const float*)d_in[9];
    const float* bo = (const float*)d_in[10];
    const float* c1 = (const float*)d_in[11];
    const float* c2 = (const float*)d_in[12];
    const float* c3 = (const float*)d_in[13];
    float* out = (float*)d_out;
    int n = in_sizes[0];
    int blocks = (n + 255) / 256;
    lorenz_pinn_kernel<<<blocks, 256>>>(t, W1, b1, W2, b2, W3, b3, W4, b4,
                                        Wo, bo, c1, c2, c3, out, n);
}